// round 1
// baseline (speedup 1.0000x reference)
#include <cuda_runtime.h>
#include <math.h>

#define N_NODES 50000
#define DIM     128

// ---------------- scratch (device globals; no allocation allowed) -------------
// typ: 0 = user, 1 = news
__device__ __align__(16) float g_aggx [2][N_NODES * DIM];
__device__ __align__(16) float g_aggh [2][N_NODES * DIM];
__device__ __align__(16) float g_agghr[2][N_NODES * DIM];
__device__ __align__(16) float g_z    [2][N_NODES * DIM];
__device__ __align__(16) float g_hr   [2][N_NODES * DIM];
__device__ __align__(16) float g_cx   [2][N_NODES * DIM];
__device__ float g_deg[2][N_NODES];
__device__ __align__(16) float g_Wbig[2][512 * 384];   // [aggx|x|aggh|h] -> [z|r|cx]
__device__ __align__(16) float g_W5  [2][256 * 128];   // [agghr|hr] -> ch
__device__ float g_bias [2][3][DIM];                   // z, r, cx biases
__device__ float g_bias5[2][DIM];

// ---------------- zero scratch -------------------------------------------------
__global__ void k_zero() {
    int idx = blockIdx.x * blockDim.x + threadIdx.x;
    if (idx < N_NODES * DIM) {
        g_aggx[0][idx] = 0.f; g_aggx[1][idx] = 0.f;
        g_aggh[0][idx] = 0.f; g_aggh[1][idx] = 0.f;
        g_agghr[0][idx] = 0.f; g_agghr[1][idx] = 0.f;
    }
    if (idx < N_NODES) { g_deg[0][idx] = 0.f; g_deg[1][idx] = 0.f; }
}

// ---------------- degree histogram ---------------------------------------------
__global__ void k_deg(const int* __restrict__ dst_un, const int* __restrict__ dst_nu, int E) {
    int e = blockIdx.x * blockDim.x + threadIdx.x;
    if (e < E) {
        atomicAdd(&g_deg[1][dst_un[e]], 1.f);   // news is dst of un edges
        atomicAdd(&g_deg[0][dst_nu[e]], 1.f);   // user is dst of nu edges
    }
}

// ---------------- scatter x & h features (one warp per edge, float4 atomics) ----
template <int TYP>
__global__ void k_scatter_xh(const float* __restrict__ xsrc, const float* __restrict__ hsrc,
                             const int* __restrict__ src, const int* __restrict__ dst, int E) {
    long t = (long)blockIdx.x * blockDim.x + threadIdx.x;
    int e = (int)(t >> 5);
    int lane = (int)(t & 31);
    if (e >= E) return;
    int s = __ldg(src + e);
    int d = __ldg(dst + e);
    float4 vx = ((const float4*)(xsrc + (size_t)s * DIM))[lane];
    float4 vh = ((const float4*)(hsrc + (size_t)s * DIM))[lane];
    atomicAdd(((float4*)(g_aggx[TYP] + (size_t)d * DIM)) + lane, vx);
    atomicAdd(((float4*)(g_aggh[TYP] + (size_t)d * DIM)) + lane, vh);
}

// ---------------- scatter h*r features ------------------------------------------
template <int TYP>
__global__ void k_scatter_hr(const int* __restrict__ src, const int* __restrict__ dst, int E) {
    long t = (long)blockIdx.x * blockDim.x + threadIdx.x;
    int e = (int)(t >> 5);
    int lane = (int)(t & 31);
    if (e >= E) return;
    int s = __ldg(src + e);
    int d = __ldg(dst + e);
    const float* f = g_hr[1 - TYP];   // source features are the *other* node type's h*r
    float4 v = ((const float4*)(f + (size_t)s * DIM))[lane];
    atomicAdd(((float4*)(g_agghr[TYP] + (size_t)d * DIM)) + lane, v);
}

// ---------------- normalize sums -> means ----------------------------------------
template <int WHICH>   // 0: aggx+aggh, 1: agghr
__global__ void k_norm() {
    int idx = blockIdx.x * blockDim.x + threadIdx.x;
    if (idx >= N_NODES * DIM) return;
    int row = idx >> 7;
    float i0 = 1.f / fmaxf(g_deg[0][row], 1.f);
    float i1 = 1.f / fmaxf(g_deg[1][row], 1.f);
    if (WHICH == 0) {
        g_aggx[0][idx] *= i0; g_aggh[0][idx] *= i0;
        g_aggx[1][idx] *= i1; g_aggh[1][idx] *= i1;
    } else {
        g_agghr[0][idx] *= i0;
        g_agghr[1][idx] *= i1;
    }
}

// ---------------- weight / bias repack --------------------------------------------
// Wl, Wr: [6][2][128][128]; b: [6][2][128]
// Wbig[t] rows: 0-127 aggx, 128-255 x, 256-383 aggh, 384-511 h
// Wbig[t] cols: 0-127 z-pre, 128-255 r-pre, 256-383 cx  (aggh/h rows zero for cx)
__global__ void k_repack(const float* __restrict__ Wl, const float* __restrict__ Wr,
                         const float* __restrict__ b) {
    int idx = blockIdx.x * blockDim.x + threadIdx.x;
    const int TOT_BIG = 2 * 512 * 384;
    const int TOT_W5  = 2 * 256 * 128;
    if (idx < TOT_BIG) {
        int t = idx / (512 * 384);
        int rem = idx % (512 * 384);
        int r = rem / 384, c = rem % 384;
        int wi = 1 - t;                    // user outputs use weight index 1, news 0
        int rb = r >> 7, rr = r & 127;
        int cb = c >> 7, cc = c & 127;
        float v = 0.f;
        if (rb == 0)      { int g = cb * 2;     v = Wl[((g * 2 + wi) * 128 + rr) * 128 + cc]; }
        else if (rb == 1) { int g = cb * 2;     v = Wr[((g * 2 + wi) * 128 + rr) * 128 + cc]; }
        else if (rb == 2) { if (cb < 2) { int g = cb * 2 + 1; v = Wl[((g * 2 + wi) * 128 + rr) * 128 + cc]; } }
        else              { if (cb < 2) { int g = cb * 2 + 1; v = Wr[((g * 2 + wi) * 128 + rr) * 128 + cc]; } }
        g_Wbig[t][r * 384 + c] = v;
        return;
    }
    int i2 = idx - TOT_BIG;
    if (i2 < TOT_W5) {
        int t = i2 / (256 * 128);
        int rem = i2 % (256 * 128);
        int r = rem / 128, c = rem % 128;
        int wi = 1 - t;
        float v = (r < 128) ? Wl[((5 * 2 + wi) * 128 + r) * 128 + c]
                            : Wr[((5 * 2 + wi) * 128 + (r - 128)) * 128 + c];
        g_W5[t][r * 128 + c] = v;
        return;
    }
    int i3 = i2 - TOT_W5;
    if (i3 < 2 * 128) {
        int t = i3 / 128, c = i3 % 128;
        int wi = 1 - t;
        g_bias[t][0][c] = b[(0 * 2 + wi) * 128 + c] + b[(1 * 2 + wi) * 128 + c];
        g_bias[t][1][c] = b[(2 * 2 + wi) * 128 + c] + b[(3 * 2 + wi) * 128 + c];
        g_bias[t][2][c] = b[(4 * 2 + wi) * 128 + c];
        g_bias5[t][c]   = b[(5 * 2 + wi) * 128 + c];
    }
}

__device__ __forceinline__ float sigmoidf_(float v) { return 1.f / (1.f + expf(-v)); }

// ---------------- fused GEMM pass A: [aggx|x|aggh|h](512) @ Wbig(512x384) ---------
// col tile 0 -> z = sigmoid(.)   ; col tile 1 -> r = sigmoid(.), store hr = h*r
// col tile 2 -> cx               . BM=BN=128, BK=16, 256 threads, 8x8 per thread.
template <int TYP>
__global__ void __launch_bounds__(256) k_gemmA(const float* __restrict__ xself,
                                               const float* __restrict__ hself) {
    __shared__ float As[16][128];
    __shared__ float Bs[16][128];
    int tid = threadIdx.x;
    int tx = tid & 15, ty = tid >> 4;
    int rowBase = blockIdx.x * 128;
    int ct = blockIdx.y;
    int colBase = ct * 128;

    const float* aggx = g_aggx[TYP];
    const float* aggh = g_aggh[TYP];
    const float* Wb = g_Wbig[TYP];

    float acc[8][8];
#pragma unroll
    for (int i = 0; i < 8; i++)
#pragma unroll
        for (int j = 0; j < 8; j++) acc[i][j] = 0.f;

    for (int kt = 0; kt < 32; ++kt) {
        int srcm = kt >> 3;
        const float* Asrc = (srcm == 0) ? aggx : (srcm == 1) ? xself : (srcm == 2) ? aggh : hself;
        int kcol = (kt & 7) * 16;
#pragma unroll
        for (int i = 0; i < 2; i++) {
            int row = i * 64 + (tid >> 2);
            int kq = (tid & 3) * 4;
            int grow = rowBase + row;
            float4 v = make_float4(0.f, 0.f, 0.f, 0.f);
            if (grow < N_NODES) v = *(const float4*)(Asrc + (size_t)grow * 128 + kcol + kq);
            As[kq + 0][row] = v.x; As[kq + 1][row] = v.y;
            As[kq + 2][row] = v.z; As[kq + 3][row] = v.w;
        }
#pragma unroll
        for (int i = 0; i < 2; i++) {
            int r = i * 8 + (tid >> 5);
            int c = (tid & 31) * 4;
            float4 v = *(const float4*)(Wb + (size_t)(kt * 16 + r) * 384 + colBase + c);
            *(float4*)(&Bs[r][c]) = v;
        }
        __syncthreads();
#pragma unroll
        for (int kk = 0; kk < 16; kk++) {
            float a[8], bb[8];
#pragma unroll
            for (int i = 0; i < 8; i++) a[i] = As[kk][ty * 8 + i];
#pragma unroll
            for (int j = 0; j < 8; j++) bb[j] = Bs[kk][tx * 8 + j];
#pragma unroll
            for (int i = 0; i < 8; i++)
#pragma unroll
                for (int j = 0; j < 8; j++) acc[i][j] += a[i] * bb[j];
        }
        __syncthreads();
    }

    const float* bias = g_bias[TYP][ct];
#pragma unroll
    for (int i = 0; i < 8; i++) {
        int grow = rowBase + ty * 8 + i;
        if (grow >= N_NODES) continue;
#pragma unroll
        for (int j = 0; j < 8; j++) {
            int c = tx * 8 + j;
            float v = acc[i][j] + bias[c];
            size_t off = (size_t)grow * 128 + c;
            if (ct == 0) {
                g_z[TYP][off] = sigmoidf_(v);
            } else if (ct == 1) {
                float r = sigmoidf_(v);
                g_hr[TYP][off] = hself[off] * r;
            } else {
                g_cx[TYP][off] = v;
            }
        }
    }
}

// ---------------- fused GEMM pass B: [agghr|hr](256) @ W5(256x128) + GRU blend ----
template <int TYP>
__global__ void __launch_bounds__(256) k_gemmB(const float* __restrict__ hself,
                                               float* __restrict__ out) {
    __shared__ float As[16][128];
    __shared__ float Bs[16][128];
    int tid = threadIdx.x;
    int tx = tid & 15, ty = tid >> 4;
    int rowBase = blockIdx.x * 128;

    const float* agghr = g_agghr[TYP];
    const float* hrs = g_hr[TYP];
    const float* W = g_W5[TYP];

    float acc[8][8];
#pragma unroll
    for (int i = 0; i < 8; i++)
#pragma unroll
        for (int j = 0; j < 8; j++) acc[i][j] = 0.f;

    for (int kt = 0; kt < 16; ++kt) {
        const float* Asrc = (kt < 8) ? agghr : hrs;
        int kcol = (kt & 7) * 16;
#pragma unroll
        for (int i = 0; i < 2; i++) {
            int row = i * 64 + (tid >> 2);
            int kq = (tid & 3) * 4;
            int grow = rowBase + row;
            float4 v = make_float4(0.f, 0.f, 0.f, 0.f);
            if (grow < N_NODES) v = *(const float4*)(Asrc + (size_t)grow * 128 + kcol + kq);
            As[kq + 0][row] = v.x; As[kq + 1][row] = v.y;
            As[kq + 2][row] = v.z; As[kq + 3][row] = v.w;
        }
#pragma unroll
        for (int i = 0; i < 2; i++) {
            int r = i * 8 + (tid >> 5);
            int c = (tid & 31) * 4;
            float4 v = *(const float4*)(W + (size_t)(kt * 16 + r) * 128 + c);
            *(float4*)(&Bs[r][c]) = v;
        }
        __syncthreads();
#pragma unroll
        for (int kk = 0; kk < 16; kk++) {
            float a[8], bb[8];
#pragma unroll
            for (int i = 0; i < 8; i++) a[i] = As[kk][ty * 8 + i];
#pragma unroll
            for (int j = 0; j < 8; j++) bb[j] = Bs[kk][tx * 8 + j];
#pragma unroll
            for (int i = 0; i < 8; i++)
#pragma unroll
                for (int j = 0; j < 8; j++) acc[i][j] += a[i] * bb[j];
        }
        __syncthreads();
    }

    const float* bias = g_bias5[TYP];
#pragma unroll
    for (int i = 0; i < 8; i++) {
        int grow = rowBase + ty * 8 + i;
        if (grow >= N_NODES) continue;
#pragma unroll
        for (int j = 0; j < 8; j++) {
            int c = tx * 8 + j;
            size_t off = (size_t)grow * 128 + c;
            float ch = acc[i][j] + bias[c];
            float ht = tanhf(g_cx[TYP][off] + ch);
            float z = g_z[TYP][off];
            out[off] = z * hself[off] + (1.f - z) * ht;
        }
    }
}

// ---------------- launch ------------------------------------------------------------
extern "C" void kernel_launch(void* const* d_in, const int* in_sizes, int n_in,
                              void* d_out, int out_size) {
    const float* x_user = (const float*)d_in[0];
    const float* x_news = (const float*)d_in[1];
    const float* h_user = (const float*)d_in[2];
    const float* h_news = (const float*)d_in[3];
    const float* Wl     = (const float*)d_in[4];
    const float* Wr     = (const float*)d_in[5];
    const float* b      = (const float*)d_in[6];
    const int* src_un   = (const int*)d_in[7];
    const int* dst_un   = (const int*)d_in[8];
    const int* src_nu   = (const int*)d_in[9];
    const int* dst_nu   = (const int*)d_in[10];
    float* out = (float*)d_out;
    const int E = in_sizes[7];

    const int nElem = N_NODES * DIM;
    k_zero<<<(nElem + 255) / 256, 256>>>();
    k_repack<<<(2 * 512 * 384 + 2 * 256 * 128 + 2 * 128 + 255) / 256, 256>>>(Wl, Wr, b);
    k_deg<<<(E + 255) / 256, 256>>>(dst_un, dst_nu, E);

    long th = (long)E * 32;
    int sblocks = (int)((th + 255) / 256);
    k_scatter_xh<1><<<sblocks, 256>>>(x_user, h_user, src_un, dst_un, E);
    k_scatter_xh<0><<<sblocks, 256>>>(x_news, h_news, src_nu, dst_nu, E);
    k_norm<0><<<(nElem + 255) / 256, 256>>>();

    dim3 gA((N_NODES + 127) / 128, 3);
    k_gemmA<0><<<gA, 256>>>(x_user, h_user);
    k_gemmA<1><<<gA, 256>>>(x_news, h_news);

    k_scatter_hr<0><<<sblocks, 256>>>(src_nu, dst_nu, E);
    k_scatter_hr<1><<<sblocks, 256>>>(src_un, dst_un, E);
    k_norm<1><<<(nElem + 255) / 256, 256>>>();

    dim3 gB((N_NODES + 127) / 128, 1);
    k_gemmB<0><<<gB, 256>>>(h_user, out);
    k_gemmB<1><<<gB, 256>>>(h_news, out + (size_t)N_NODES * DIM);
}